// round 3
// baseline (speedup 1.0000x reference)
#include <cuda_runtime.h>
#include <math.h>

// ---------------------------------------------------------------------------
// AECFModel fused multimodal classifier — fp32 baseline with algebraic folding.
// H=256, ID=TD=512, NC=80, NH=4, HD=64, B=131072.
// ---------------------------------------------------------------------------

// Per-launch precomputed tensors (device-global scratch; rewritten every call).
__device__ float g_q[256];          // fusion_query @ Wq + bq
__device__ float g_wk[4 * 256];     // wk[h][j] = sum_d Wk[j, h*64+d] * q[h*64+d]
__device__ float g_ck[4];           // ck[h]    = sum_d bk[h*64+d]    * q[h*64+d]
__device__ float g_tmp[256];        // bv @ Wo + bo
__device__ float g_Wof[256 * 512];  // Wo @ W_fp
__device__ float g_bof[512];        // (bv@Wo+bo) @ W_fp + b_fp

// ------------------------------ setup kernels ------------------------------

__global__ void setup_q(const float* __restrict__ fq, const float* __restrict__ Wq,
                        const float* __restrict__ bq) {
    __shared__ float red[256];
    int jl = threadIdx.x & 31;
    int kp = threadIdx.x >> 5;
    int j  = blockIdx.x * 32 + jl;
    float s = 0.f;
    for (int k = kp * 32; k < kp * 32 + 32; k++)
        s = fmaf(fq[k], Wq[k * 256 + j], s);
    red[threadIdx.x] = s;
    __syncthreads();
    if (kp == 0) {
        float t = bq[j];
#pragma unroll
        for (int p = 0; p < 8; p++) t += red[p * 32 + jl];
        g_q[j] = t;
    }
}

__global__ void setup_wk(const float* __restrict__ Wk, const float* __restrict__ bk) {
    int idx = blockIdx.x * 128 + threadIdx.x;  // 0..1023
    int h = idx >> 8, j = idx & 255;
    float s = 0.f;
#pragma unroll 4
    for (int d = 0; d < 64; d++)
        s = fmaf(Wk[j * 256 + h * 64 + d], g_q[h * 64 + d], s);
    g_wk[h * 256 + j] = s;
    if (blockIdx.x == 0 && threadIdx.x < 4) {
        int hh = threadIdx.x;
        float c = 0.f;
        for (int d = 0; d < 64; d++) c = fmaf(bk[hh * 64 + d], g_q[hh * 64 + d], c);
        g_ck[hh] = c;
    }
}

__global__ void setup_bvo(const float* __restrict__ bv, const float* __restrict__ Wo,
                          const float* __restrict__ bo) {
    int j = threadIdx.x;
    float s = bo[j];
    for (int k = 0; k < 256; k++) s = fmaf(bv[k], Wo[k * 256 + j], s);
    g_tmp[j] = s;
}

__global__ void setup_bof(const float* __restrict__ Wfp, const float* __restrict__ bfp) {
    __shared__ float red[256];
    int jl = threadIdx.x & 127;
    int p  = threadIdx.x >> 7;
    int j  = blockIdx.x * 128 + jl;
    float s = 0.f;
    for (int m = p * 128; m < p * 128 + 128; m++)
        s = fmaf(g_tmp[m], Wfp[m * 512 + j], s);
    red[threadIdx.x] = s;
    __syncthreads();
    if (p == 0) g_bof[j] = bfp[j] + red[jl] + red[128 + jl];
}

// Wof = Wo[256,256] @ Wfp[256,512]. grid = 16 (4 i-tiles x 4 j-tiles), 256 thr.
__global__ void setup_wof(const float* __restrict__ Wo, const float* __restrict__ Wfp) {
    __shared__ float sA[64 * 65];
    int tx = threadIdx.x & 31, ty = threadIdx.x >> 5;
    int it = blockIdx.x >> 2, jt = blockIdx.x & 3;
    float acc[8][4];
#pragma unroll
    for (int i = 0; i < 8; i++)
#pragma unroll
        for (int c = 0; c < 4; c++) acc[i][c] = 0.f;

    for (int mc = 0; mc < 256; mc += 64) {
        __syncthreads();
#pragma unroll
        for (int l = 0; l < 16; l++) {
            int idx = threadIdx.x + l * 256;
            int r = idx >> 6, k = idx & 63;
            sA[r * 65 + k] = Wo[(it * 64 + r) * 256 + mc + k];
        }
        __syncthreads();
#pragma unroll 2
        for (int k = 0; k < 64; k++) {
            const float* Wp = Wfp + (size_t)(mc + k) * 512 + jt * 128 + tx;
            float w[4];
#pragma unroll
            for (int c = 0; c < 4; c++) w[c] = Wp[c * 32];
#pragma unroll
            for (int i = 0; i < 8; i++) {
                float a = sA[(ty * 8 + i) * 65 + k];
#pragma unroll
                for (int c = 0; c < 4; c++) acc[i][c] = fmaf(a, w[c], acc[i][c]);
            }
        }
    }
    __syncthreads();
#pragma unroll
    for (int i = 0; i < 8; i++)
#pragma unroll
        for (int c = 0; c < 4; c++)
            g_Wof[(size_t)(it * 64 + ty * 8 + i) * 512 + jt * 128 + tx + 32 * c] =
                acc[i][c];
}

// ------------------------------- main kernel -------------------------------
// 64 rows/block, 256 threads, 216320 B dynamic smem, 1 CTA/SM.
//
// smem (float offsets):
//   buf0 @ 0      [64][257]  enc_img  -> masked xi
//   buf1 @ 16448  [64][257]  enc_txt  -> masked xt
//   buf2 @ 32896  [64][257]  xp (masked attn-pooled)
//   sA   @ 49344  [64][65]   staging
//   attn @ 53504  [64][4]    a0 per (row, head)
//   flag @ 53760  [64] int   0 none / 1 both / 2 img / 3 txt
//   ssq  @ 53824  [256]
//   -- overlays after fused GEMM --
//   fused @ 0     [64] stride 513  (ends 32832)
//   h1    @ 32896 [64][257]        (ends 49344)

#define SMEM_FLOATS 54080
#define SMEM_BYTES  (SMEM_FLOATS * 4)

__global__ void __launch_bounds__(256, 1)
fused_main(const float* __restrict__ img, const float* __restrict__ txt,
           const float* __restrict__ W_ie, const float* __restrict__ b_ie,
           const float* __restrict__ W_te, const float* __restrict__ b_te,
           const float* __restrict__ Wv,
           const float* __restrict__ W_ip, const float* __restrict__ b_ip,
           const float* __restrict__ W_tp, const float* __restrict__ b_tp,
           const float* __restrict__ Wc1,  const float* __restrict__ bc1,
           const float* __restrict__ Wc2,  const float* __restrict__ bc2,
           float* __restrict__ out) {
    extern __shared__ float sm[];
    float* buf0  = sm;
    float* buf1  = sm + 16448;
    float* buf2  = sm + 32896;
    float* sA    = sm + 49344;
    float* sattn = sm + 53504;
    int*   sflag = (int*)(sm + 53760);
    float* ssq   = sm + 53824;
    float* fused = sm;          // stride 513 (overlays buf0/buf1)
    float* h1    = sm + 32896;  // stride 257 (overlays buf2)

    const int tid = threadIdx.x;
    const int tx = tid & 31, ty = tid >> 5;
    const size_t row0 = (size_t)blockIdx.x * 64;

    // ---------------- P1: encoders (img then txt) + presence flags ---------
    for (int mod = 0; mod < 2; mod++) {
        const float* X  = mod ? txt  : img;
        const float* W  = mod ? W_te : W_ie;
        const float* bb = mod ? b_te : b_ie;
        float* enc = mod ? buf1 : buf0;

        float acc[8][8];
#pragma unroll
        for (int i = 0; i < 8; i++)
#pragma unroll
            for (int c = 0; c < 8; c++) acc[i][c] = 0.f;
        float sq = 0.f;

        for (int kc = 0; kc < 512; kc += 64) {
            __syncthreads();
#pragma unroll
            for (int l = 0; l < 4; l++) {
                int idx = tid + l * 256;          // 0..1023 float4 slots
                int r = idx >> 4, k4 = idx & 15;
                float4 v = *(const float4*)(X + (row0 + r) * 512 + kc + k4 * 4);
                float* d = sA + r * 65 + k4 * 4;
                d[0] = v.x; d[1] = v.y; d[2] = v.z; d[3] = v.w;
            }
            __syncthreads();
            {
                int rr = tid >> 2, pp = tid & 3;
#pragma unroll
                for (int u = 0; u < 16; u++) {
                    float v = sA[rr * 65 + pp * 16 + u];
                    sq = fmaf(v, v, sq);
                }
            }
#pragma unroll 2
            for (int k = 0; k < 64; k++) {
                const float4* Wp = (const float4*)(W + (size_t)(kc + k) * 256 + tx * 8);
                float4 w0 = Wp[0], w1 = Wp[1];
                float w[8] = {w0.x, w0.y, w0.z, w0.w, w1.x, w1.y, w1.z, w1.w};
#pragma unroll
                for (int i = 0; i < 8; i++) {
                    float a = sA[(ty * 8 + i) * 65 + k];
#pragma unroll
                    for (int c = 0; c < 8; c++) acc[i][c] = fmaf(a, w[c], acc[i][c]);
                }
            }
        }
#pragma unroll
        for (int i = 0; i < 8; i++) {
            int r = ty * 8 + i;
#pragma unroll
            for (int c = 0; c < 8; c++) {
                int j = tx * 8 + c;
                float v = acc[i][c] + bb[j];
                enc[r * 257 + j] = v > 0.f ? v : 0.f;
            }
        }
        __syncthreads();
        ssq[tid] = sq;
        __syncthreads();
        if (tid < 64) {
            float t = ssq[tid * 4] + ssq[tid * 4 + 1] + ssq[tid * 4 + 2] + ssq[tid * 4 + 3];
            int f = (t > 1e-12f) ? 1 : 0;  // norm > 1e-6
            if (mod == 0) {
                sflag[tid] = f;
            } else {
                int fi = sflag[tid];
                sflag[tid] = (fi && f) ? 1 : (fi ? 2 : (f ? 3 : 0));
            }
        }
        __syncthreads();
    }

    // ---------------- P2: attention scores + softmax (folded K-proj) -------
    {
        int r = tid >> 2, h = tid & 3;  // 64 rows x 4 heads = 256 threads
        float di = 0.f, dt = 0.f;
        const float* wkp = g_wk + h * 256;
#pragma unroll 4
        for (int j = 0; j < 256; j++) {
            float w = wkp[j];
            di = fmaf(buf0[r * 257 + j], w, di);
            dt = fmaf(buf1[r * 257 + j], w, dt);
        }
        float s0 = (di + g_ck[h]) * 0.125f;
        float s1 = (dt + g_ck[h]) * 0.125f;
        float m  = fmaxf(s0, s1);
        float e0 = expf(s0 - m), e1 = expf(s1 - m);
        sattn[r * 4 + h] = e0 / (e0 + e1);  // a0; a1 = 1 - a0
    }
    __syncthreads();

    // ---------------- P3: attn-pooled V, head-tiled (xp = masked pooled) ---
    for (int h = 0; h < 4; h++) {
        float pacc[8][2];
#pragma unroll
        for (int i = 0; i < 8; i++) { pacc[i][0] = 0.f; pacc[i][1] = 0.f; }

        for (int kc = 0; kc < 256; kc += 64) {
            __syncthreads();
#pragma unroll
            for (int l = 0; l < 16; l++) {
                int idx = tid + l * 256;
                int r = idx >> 6, k = idx & 63;
                float a0 = sattn[r * 4 + h];
                float e0 = buf0[r * 257 + kc + k];
                float e1 = buf1[r * 257 + kc + k];
                sA[r * 65 + k] = e1 + a0 * (e0 - e1);  // a0*e0 + (1-a0)*e1
            }
            __syncthreads();
#pragma unroll 2
            for (int k = 0; k < 64; k++) {
                const float* Wp = Wv + (size_t)(kc + k) * 256 + h * 64 + tx;
                float w0 = Wp[0], w1 = Wp[32];
#pragma unroll
                for (int i = 0; i < 8; i++) {
                    float a = sA[(ty * 8 + i) * 65 + k];
                    pacc[i][0] = fmaf(a, w0, pacc[i][0]);
                    pacc[i][1] = fmaf(a, w1, pacc[i][1]);
                }
            }
        }
#pragma unroll
        for (int i = 0; i < 8; i++) {
            int r = ty * 8 + i;
            float msk = (sflag[r] == 1) ? 1.f : 0.f;
            buf2[r * 257 + h * 64 + tx]      = pacc[i][0] * msk;
            buf2[r * 257 + h * 64 + tx + 32] = pacc[i][1] * msk;
        }
    }
    __syncthreads();

    // ---------------- P4: mask xi / xt in place ----------------------------
    for (int idx = tid; idx < 64 * 256; idx += 256) {
        int r = idx >> 8, j = idx & 255;
        int fl = sflag[r];
        if (fl != 2) buf0[r * 257 + j] = 0.f;
        if (fl != 3) buf1[r * 257 + j] = 0.f;
    }
    __syncthreads();

    // ---------------- P5: unified fused GEMM, K = 3*256, N = 512 -----------
    float facc[8][16];
#pragma unroll
    for (int i = 0; i < 8; i++)
#pragma unroll
        for (int u = 0; u < 16; u++) facc[i][u] = 0.f;

    for (int seg = 0; seg < 3; seg++) {
        const float* xb = (seg == 0) ? buf2 : (seg == 1) ? buf0 : buf1;
        const float* Wb = (seg == 0) ? g_Wof : (seg == 1) ? W_ip : W_tp;
        for (int k = 0; k < 256; k++) {
            const float4* Wp = (const float4*)(Wb + (size_t)k * 512 + tx * 16);
            float4 q0 = Wp[0], q1 = Wp[1], q2 = Wp[2], q3 = Wp[3];
            float w[16] = {q0.x, q0.y, q0.z, q0.w, q1.x, q1.y, q1.z, q1.w,
                           q2.x, q2.y, q2.z, q2.w, q3.x, q3.y, q3.z, q3.w};
#pragma unroll
            for (int i = 0; i < 8; i++) {
                float a = xb[(ty * 8 + i) * 257 + k];
#pragma unroll
                for (int u = 0; u < 16; u++) facc[i][u] = fmaf(a, w[u], facc[i][u]);
            }
        }
    }
    __syncthreads();  // all reads of buf0/1/2 done before overlay write
#pragma unroll
    for (int i = 0; i < 8; i++) {
        int r = ty * 8 + i;
        int fl = sflag[r];
        const float* bsel = (fl == 1) ? g_bof : (fl == 2) ? b_ip
                          : (fl == 3) ? b_tp : (const float*)0;
#pragma unroll
        for (int u = 0; u < 16; u++) {
            float b = bsel ? bsel[tx * 16 + u] : 0.f;
            fused[r * 513 + tx * 16 + u] = facc[i][u] + b;
        }
    }
    __syncthreads();

    // ---------------- P6: classifier layer 1 (512 -> 256, ReLU) ------------
    {
        float cacc[8][8];
#pragma unroll
        for (int i = 0; i < 8; i++)
#pragma unroll
            for (int c = 0; c < 8; c++) cacc[i][c] = 0.f;
#pragma unroll 2
        for (int k = 0; k < 512; k++) {
            const float4* Wp = (const float4*)(Wc1 + (size_t)k * 256 + tx * 8);
            float4 w0 = Wp[0], w1 = Wp[1];
            float w[8] = {w0.x, w0.y, w0.z, w0.w, w1.x, w1.y, w1.z, w1.w};
#pragma unroll
            for (int i = 0; i < 8; i++) {
                float a = fused[(ty * 8 + i) * 513 + k];
#pragma unroll
                for (int c = 0; c < 8; c++) cacc[i][c] = fmaf(a, w[c], cacc[i][c]);
            }
        }
        __syncthreads();
#pragma unroll
        for (int i = 0; i < 8; i++) {
            int r = ty * 8 + i;
#pragma unroll
            for (int c = 0; c < 8; c++) {
                int j = tx * 8 + c;
                float v = cacc[i][c] + bc1[j];
                h1[r * 257 + j] = v > 0.f ? v : 0.f;
            }
        }
        __syncthreads();
    }

    // ---------------- P7: classifier layer 2 (256 -> 80) -------------------
    {
        float lacc[8][3];
#pragma unroll
        for (int i = 0; i < 8; i++) { lacc[i][0] = lacc[i][1] = lacc[i][2] = 0.f; }
#pragma unroll 2
        for (int k = 0; k < 256; k++) {
            const float* Wp = Wc2 + (size_t)k * 80 + tx;
            float w0 = Wp[0];
            float w1 = Wp[32];
            float w2 = (tx < 16) ? Wp[64] : 0.f;
#pragma unroll
            for (int i = 0; i < 8; i++) {
                float a = h1[(ty * 8 + i) * 257 + k];
                lacc[i][0] = fmaf(a, w0, lacc[i][0]);
                lacc[i][1] = fmaf(a, w1, lacc[i][1]);
                lacc[i][2] = fmaf(a, w2, lacc[i][2]);
            }
        }
#pragma unroll
        for (int i = 0; i < 8; i++) {
            size_t r = row0 + ty * 8 + i;
            out[r * 80 + tx]      = lacc[i][0] + bc2[tx];
            out[r * 80 + tx + 32] = lacc[i][1] + bc2[tx + 32];
            if (tx < 16)
                out[r * 80 + tx + 64] = lacc[i][2] + bc2[tx + 64];
        }
    }
}

// ------------------------------- launch ------------------------------------

extern "C" void kernel_launch(void* const* d_in, const int* in_sizes, int n_in,
                              void* d_out, int out_size) {
    const float* img  = (const float*)d_in[0];
    const float* txt  = (const float*)d_in[1];
    const float* W_ie = (const float*)d_in[2];
    const float* b_ie = (const float*)d_in[3];
    const float* W_te = (const float*)d_in[4];
    const float* b_te = (const float*)d_in[5];
    const float* fq   = (const float*)d_in[6];
    const float* Wq   = (const float*)d_in[7];
    const float* bq   = (const float*)d_in[8];
    const float* Wk   = (const float*)d_in[9];
    const float* bk   = (const float*)d_in[10];
    const float* Wv   = (const float*)d_in[11];
    const float* bv   = (const float*)d_in[12];
    const float* Wo   = (const float*)d_in[13];
    const float* bo   = (const float*)d_in[14];
    const float* W_ip = (const float*)d_in[15];
    const float* b_ip = (const float*)d_in[16];
    const float* W_tp = (const float*)d_in[17];
    const float* b_tp = (const float*)d_in[18];
    const float* W_fp = (const float*)d_in[19];
    const float* b_fp = (const float*)d_in[20];
    const float* Wc1  = (const float*)d_in[21];
    const float* bc1  = (const float*)d_in[22];
    const float* Wc2  = (const float*)d_in[23];
    const float* bc2  = (const float*)d_in[24];
    float* out = (float*)d_out;

    const int B = in_sizes[0] / 512;

    setup_q  <<<8, 256>>>(fq, Wq, bq);
    setup_wk <<<8, 128>>>(Wk, bk);
    setup_bvo<<<1, 256>>>(bv, Wo, bo);
    setup_bof<<<4, 256>>>(W_fp, b_fp);
    setup_wof<<<16, 256>>>(Wo, W_fp);

    cudaFuncSetAttribute(fused_main, cudaFuncAttributeMaxDynamicSharedMemorySize,
                         SMEM_BYTES);
    fused_main<<<B / 64, 256, SMEM_BYTES>>>(
        img, txt, W_ie, b_ie, W_te, b_te, Wv,
        W_ip, b_ip, W_tp, b_tp, Wc1, bc1, Wc2, bc2, out);
}

// round 4
// speedup vs baseline: 1.3238x; 1.3238x over previous
#include <cuda_runtime.h>
#include <math.h>

// ---------------------------------------------------------------------------
// AECFModel fused multimodal classifier — fp32 + f32x2 packed FMA + branch sort.
// H=256, ID=TD=512, NC=80, NH=4, HD=64, B=131072.
// ---------------------------------------------------------------------------

typedef unsigned long long u64;

__device__ __forceinline__ u64 pk2(float x, float y) {
    u64 r; asm("mov.b64 %0,{%1,%2};" : "=l"(r) : "f"(x), "f"(y)); return r;
}
__device__ __forceinline__ void fma2(u64& d, u64 a, u64 b) {
    asm("fma.rn.f32x2 %0,%1,%2,%0;" : "+l"(d) : "l"(a), "l"(b));
}
__device__ __forceinline__ float2 up2(u64 d) {
    float2 r; asm("mov.b64 {%0,%1},%2;" : "=f"(r.x), "=f"(r.y) : "l"(d)); return r;
}

// Per-launch precomputed tensors (device-global scratch; rewritten every call).
__device__ float g_q[256];          // fusion_query @ Wq + bq
__device__ float g_wk[4 * 256];     // wk[h][j] = sum_d Wk[j, h*64+d] * q[h*64+d]
__device__ float g_ck[4];           // ck[h]    = sum_d bk[h*64+d]    * q[h*64+d]
__device__ float g_tmp[256];        // bv @ Wo + bo
__device__ float g_Wof[256 * 512];  // Wo @ W_fp
__device__ float g_bof[512];        // (bv@Wo+bo) @ W_fp + b_fp

// ------------------------------ setup kernels ------------------------------

// All the small precomputes in one block (1024 threads).
__global__ void setup_small(const float* __restrict__ fq, const float* __restrict__ Wq,
                            const float* __restrict__ bq, const float* __restrict__ Wk,
                            const float* __restrict__ bk, const float* __restrict__ bv,
                            const float* __restrict__ Wo, const float* __restrict__ bo,
                            const float* __restrict__ Wfp, const float* __restrict__ bfp) {
    int t = threadIdx.x;
    if (t < 256) {                       // q = fq @ Wq + bq
        float s = bq[t];
        for (int k = 0; k < 256; k++) s = fmaf(fq[k], Wq[k * 256 + t], s);
        g_q[t] = s;
    }
    __syncthreads();
    {                                    // wk[h][j], ck[h]
        int h = t >> 8, j = t & 255;
        float s = 0.f;
#pragma unroll 4
        for (int d = 0; d < 64; d++)
            s = fmaf(Wk[j * 256 + h * 64 + d], g_q[h * 64 + d], s);
        g_wk[h * 256 + j] = s;
        if (t < 4) {
            float c = 0.f;
            for (int d = 0; d < 64; d++) c = fmaf(bk[t * 64 + d], g_q[t * 64 + d], c);
            g_ck[t] = c;
        }
    }
    __syncthreads();
    if (t < 256) {                       // tmp = bv @ Wo + bo
        float s = bo[t];
        for (int k = 0; k < 256; k++) s = fmaf(bv[k], Wo[k * 256 + t], s);
        g_tmp[t] = s;
    }
    __syncthreads();
    if (t < 512) {                       // bof = tmp @ Wfp + bfp
        float s = bfp[t];
        for (int m = 0; m < 256; m++) s = fmaf(g_tmp[m], Wfp[m * 512 + t], s);
        g_bof[t] = s;
    }
}

// Wof = Wo[256,256] @ Wfp[256,512]. grid = 16 (4 i-tiles x 4 j-tiles), 256 thr.
__global__ void setup_wof(const float* __restrict__ Wo, const float* __restrict__ Wfp) {
    __shared__ float sA[64 * 65];
    int tx = threadIdx.x & 31, ty = threadIdx.x >> 5;
    int it = blockIdx.x >> 2, jt = blockIdx.x & 3;
    float acc[8][4];
#pragma unroll
    for (int i = 0; i < 8; i++)
#pragma unroll
        for (int c = 0; c < 4; c++) acc[i][c] = 0.f;

    for (int mc = 0; mc < 256; mc += 64) {
        __syncthreads();
#pragma unroll
        for (int l = 0; l < 16; l++) {
            int idx = threadIdx.x + l * 256;
            int r = idx >> 6, k = idx & 63;
            sA[r * 65 + k] = Wo[(it * 64 + r) * 256 + mc + k];
        }
        __syncthreads();
#pragma unroll 2
        for (int k = 0; k < 64; k++) {
            const float* Wp = Wfp + (size_t)(mc + k) * 512 + jt * 128 + tx;
            float w[4];
#pragma unroll
            for (int c = 0; c < 4; c++) w[c] = Wp[c * 32];
#pragma unroll
            for (int i = 0; i < 8; i++) {
                float a = sA[(ty * 8 + i) * 65 + k];
#pragma unroll
                for (int c = 0; c < 4; c++) acc[i][c] = fmaf(a, w[c], acc[i][c]);
            }
        }
    }
    __syncthreads();
#pragma unroll
    for (int i = 0; i < 8; i++)
#pragma unroll
        for (int c = 0; c < 4; c++)
            g_Wof[(size_t)(it * 64 + ty * 8 + i) * 512 + jt * 128 + tx + 32 * c] =
                acc[i][c];
}

// ------------------------------- main kernel -------------------------------
// 64 rows/block, 256 threads, 1 CTA/SM.
//
// smem (float offsets):
//   buf0 @ 0      [64][257]  enc_img
//   buf1 @ 16448  [64][257]  enc_txt
//   buf2 @ 32896  [64][257]  attn-pooled
//   sA   @ 49344  [64][65]
//   attn @ 53504  [64][4]
//   flag @ 53760  [64] int
//   perm @ 53824  [64] int   sorted slot -> original row
//   sbr  @ 53888  [64] int   branch of sorted slot
//   ssq  @ 53952  [256]
//   overlays: fused @ 0 (stride 513, ends 32832), h1 @ 32896 (stride 257)

#define OFF_BUF1 16448
#define OFF_BUF2 32896
#define OFF_SA   49344
#define OFF_ATTN 53504
#define OFF_FLAG 53760
#define OFF_PERM 53824
#define OFF_SBR  53888
#define OFF_SSQ  53952
#define SMEM_FLOATS 54208
#define SMEM_BYTES (SMEM_FLOATS * 4)

// One K=256, N=512 GEMM segment; A rows selected through sperm, optional mask.
template <bool MASKED>
__device__ __forceinline__ void gemm_seg(u64 (&facc)[8][8],
                                         const float* __restrict__ Abase,
                                         const float* __restrict__ W,
                                         const int* __restrict__ sperm,
                                         const float* msk, int ty, int tx) {
    const float* arow[8];
    int s0 = ty * 8;
#pragma unroll
    for (int i = 0; i < 8; i++) arow[i] = Abase + (size_t)sperm[s0 + i] * 257;
#pragma unroll 2
    for (int k = 0; k < 256; k++) {
        const ulonglong2* Wp = (const ulonglong2*)(W + (size_t)k * 512 + tx * 16);
        ulonglong2 q0 = Wp[0], q1 = Wp[1], q2 = Wp[2], q3 = Wp[3];
        u64 wv[8] = {q0.x, q0.y, q1.x, q1.y, q2.x, q2.y, q3.x, q3.y};
#pragma unroll
        for (int i = 0; i < 8; i++) {
            float a = MASKED ? arow[i][k] * msk[i] : arow[i][k];
            u64 ap = pk2(a, a);
#pragma unroll
            for (int u = 0; u < 8; u++) fma2(facc[i][u], ap, wv[u]);
        }
    }
}

__global__ void __launch_bounds__(256)
fused_main(const float* __restrict__ img, const float* __restrict__ txt,
           const float* __restrict__ W_ie, const float* __restrict__ b_ie,
           const float* __restrict__ W_te, const float* __restrict__ b_te,
           const float* __restrict__ Wv,
           const float* __restrict__ W_ip, const float* __restrict__ b_ip,
           const float* __restrict__ W_tp, const float* __restrict__ b_tp,
           const float* __restrict__ Wc1,  const float* __restrict__ bc1,
           const float* __restrict__ Wc2,  const float* __restrict__ bc2,
           float* __restrict__ out) {
    extern __shared__ float sm[];
    float* buf0  = sm;
    float* buf1  = sm + OFF_BUF1;
    float* buf2  = sm + OFF_BUF2;
    float* sA    = sm + OFF_SA;
    float* sattn = sm + OFF_ATTN;
    int*   sflag = (int*)(sm + OFF_FLAG);
    int*   sperm = (int*)(sm + OFF_PERM);
    int*   ssbr  = (int*)(sm + OFF_SBR);
    float* ssq   = sm + OFF_SSQ;
    float* fused = sm;             // stride 513 (overlays buf0/buf1)
    float* h1    = sm + OFF_BUF2;  // stride 257 (overlays buf2)

    const int tid = threadIdx.x;
    const int tx = tid & 31, ty = tid >> 5;
    const size_t row0 = (size_t)blockIdx.x * 64;

    // ---------------- P1: encoders + presence flags ------------------------
    for (int mod = 0; mod < 2; mod++) {
        const float* X  = mod ? txt  : img;
        const float* W  = mod ? W_te : W_ie;
        const float* bb = mod ? b_te : b_ie;
        float* enc = mod ? buf1 : buf0;

        u64 acc2[8][4];
#pragma unroll
        for (int i = 0; i < 8; i++)
#pragma unroll
            for (int c = 0; c < 4; c++) acc2[i][c] = 0ULL;
        float sq = 0.f;

        for (int kc = 0; kc < 512; kc += 64) {
            __syncthreads();
#pragma unroll
            for (int l = 0; l < 4; l++) {
                int idx = tid + l * 256;          // float4 slots
                int r = idx >> 4, k4 = idx & 15;
                float4 v = *(const float4*)(X + (row0 + r) * 512 + kc + k4 * 4);
                float* d = sA + r * 65 + k4 * 4;
                d[0] = v.x; d[1] = v.y; d[2] = v.z; d[3] = v.w;
            }
            __syncthreads();
            {
                int rr = tid >> 2, pp = tid & 3;
#pragma unroll
                for (int u = 0; u < 16; u++) {
                    float v = sA[rr * 65 + pp * 16 + u];
                    sq = fmaf(v, v, sq);
                }
            }
#pragma unroll 2
            for (int k = 0; k < 64; k++) {
                const ulonglong2* Wp =
                    (const ulonglong2*)(W + (size_t)(kc + k) * 256 + tx * 8);
                ulonglong2 wa = Wp[0], wb = Wp[1];
#pragma unroll
                for (int i = 0; i < 8; i++) {
                    float a = sA[(ty * 8 + i) * 65 + k];
                    u64 ap = pk2(a, a);
                    fma2(acc2[i][0], ap, wa.x);
                    fma2(acc2[i][1], ap, wa.y);
                    fma2(acc2[i][2], ap, wb.x);
                    fma2(acc2[i][3], ap, wb.y);
                }
            }
        }
#pragma unroll
        for (int i = 0; i < 8; i++) {
            int r = ty * 8 + i;
#pragma unroll
            for (int c = 0; c < 4; c++) {
                float2 v = up2(acc2[i][c]);
                int j = tx * 8 + c * 2;
                float v0 = v.x + bb[j], v1 = v.y + bb[j + 1];
                enc[r * 257 + j]     = v0 > 0.f ? v0 : 0.f;
                enc[r * 257 + j + 1] = v1 > 0.f ? v1 : 0.f;
            }
        }
        __syncthreads();
        ssq[tid] = sq;
        __syncthreads();
        if (tid < 64) {
            float t = ssq[tid * 4] + ssq[tid * 4 + 1] + ssq[tid * 4 + 2] + ssq[tid * 4 + 3];
            int f = (t > 1e-12f) ? 1 : 0;  // norm > 1e-6
            if (mod == 0) sflag[tid] = f;
            else {
                int fi = sflag[tid];
                sflag[tid] = (fi && f) ? 1 : (fi ? 2 : (f ? 3 : 0));
            }
        }
        __syncthreads();
    }

    // ---------------- P2: folded attention scores + softmax ----------------
    {
        int r = tid >> 2, h = tid & 3;
        float di = 0.f, dt = 0.f;
        const float* wkp = g_wk + h * 256;
#pragma unroll 4
        for (int j = 0; j < 256; j++) {
            float w = wkp[j];
            di = fmaf(buf0[r * 257 + j], w, di);
            dt = fmaf(buf1[r * 257 + j], w, dt);
        }
        float s0 = (di + g_ck[h]) * 0.125f;
        float s1 = (dt + g_ck[h]) * 0.125f;
        float m  = fmaxf(s0, s1);
        float e0 = expf(s0 - m), e1 = expf(s1 - m);
        sattn[r * 4 + h] = e0 / (e0 + e1);  // a0; a1 = 1 - a0
    }
    // sort rows by branch: order both(1), img(2), txt(3), none(0)
    if (tid == 255) {
        int cnt[4] = {0, 0, 0, 0};
        for (int r = 0; r < 64; r++) cnt[sflag[r]]++;
        int base[4];
        base[1] = 0;
        base[2] = cnt[1];
        base[3] = cnt[1] + cnt[2];
        base[0] = cnt[1] + cnt[2] + cnt[3];
        for (int r = 0; r < 64; r++) {
            int f = sflag[r];
            int s = base[f]++;
            sperm[s] = r;
            ssbr[s]  = f;
        }
    }
    __syncthreads();

    // ---------------- P3: attn-pooled V (head-tiled) -----------------------
    for (int h = 0; h < 4; h++) {
        u64 pacc[8];
#pragma unroll
        for (int i = 0; i < 8; i++) pacc[i] = 0ULL;

        for (int kc = 0; kc < 256; kc += 64) {
            __syncthreads();
#pragma unroll
            for (int l = 0; l < 16; l++) {
                int idx = tid + l * 256;
                int r = idx >> 6, k = idx & 63;
                float a0 = sattn[r * 4 + h];
                float e0 = buf0[r * 257 + kc + k];
                float e1 = buf1[r * 257 + kc + k];
                sA[r * 65 + k] = e1 + a0 * (e0 - e1);
            }
            __syncthreads();
#pragma unroll 2
            for (int k = 0; k < 64; k++) {
                u64 w = *(const u64*)(Wv + (size_t)(kc + k) * 256 + h * 64 + tx * 2);
#pragma unroll
                for (int i = 0; i < 8; i++) {
                    float a = sA[(ty * 8 + i) * 65 + k];
                    fma2(pacc[i], pk2(a, a), w);
                }
            }
        }
#pragma unroll
        for (int i = 0; i < 8; i++) {
            int r = ty * 8 + i;
            float2 v = up2(pacc[i]);
            buf2[r * 257 + h * 64 + tx * 2]     = v.x;
            buf2[r * 257 + h * 64 + tx * 2 + 1] = v.y;
        }
    }
    __syncthreads();

    // ---------------- P5: branch-specialized projection GEMM ---------------
    u64 facc[8][8];
#pragma unroll
    for (int i = 0; i < 8; i++)
#pragma unroll
        for (int u = 0; u < 8; u++) facc[i][u] = 0ULL;

    {
        int b_first = ssbr[ty * 8], b_last = ssbr[ty * 8 + 7];
        if (b_first == b_last) {
            // pure warp (sorted slots): one segment, or none at all
            if (b_first == 1)
                gemm_seg<false>(facc, buf2, g_Wof, sperm, 0, ty, tx);
            else if (b_first == 2)
                gemm_seg<false>(facc, buf0, W_ip, sperm, 0, ty, tx);
            else if (b_first == 3)
                gemm_seg<false>(facc, buf1, W_tp, sperm, 0, ty, tx);
        } else {
            unsigned need = 0;
#pragma unroll
            for (int i = 0; i < 8; i++) need |= 1u << ssbr[ty * 8 + i];
            float msk[8];
            for (int seg = 1; seg <= 3; seg++) {
                if (!(need & (1u << seg))) continue;
#pragma unroll
                for (int i = 0; i < 8; i++)
                    msk[i] = (ssbr[ty * 8 + i] == seg) ? 1.f : 0.f;
                const float* A = (seg == 1) ? buf2 : (seg == 2) ? buf0 : buf1;
                const float* W = (seg == 1) ? g_Wof : (seg == 2) ? W_ip : W_tp;
                gemm_seg<true>(facc, A, W, sperm, msk, ty, tx);
            }
        }
    }
    __syncthreads();  // all reads of buf0/1/2 done before fused overlay write
#pragma unroll
    for (int i = 0; i < 8; i++) {
        int s = ty * 8 + i;
        int fl = ssbr[s];
        const float* bsel = (fl == 1) ? g_bof : (fl == 2) ? b_ip
                          : (fl == 3) ? b_tp : (const float*)0;
#pragma unroll
        for (int u = 0; u < 8; u++) {
            float2 v = up2(facc[i][u]);
            int j = tx * 16 + u * 2;
            float b0 = bsel ? bsel[j] : 0.f;
            float b1 = bsel ? bsel[j + 1] : 0.f;
            fused[s * 513 + j]     = v.x + b0;
            fused[s * 513 + j + 1] = v.y + b1;
        }
    }
    __syncthreads();

    // ---------------- P6: classifier layer 1 (512 -> 256, ReLU) ------------
    {
        u64 cacc[8][4];
#pragma unroll
        for (int i = 0; i < 8; i++)
#pragma unroll
            for (int c = 0; c < 4; c++) cacc[i][c] = 0ULL;
#pragma unroll 2
        for (int k = 0; k < 512; k++) {
            const ulonglong2* Wp = (const ulonglong2*)(Wc1 + (size_t)k * 256 + tx * 8);
            ulonglong2 wa = Wp[0], wb = Wp[1];
#pragma unroll
            for (int i = 0; i < 8; i++) {
                float a = fused[(ty * 8 + i) * 513 + k];
                u64 ap = pk2(a, a);
                fma2(cacc[i][0], ap, wa.x);
                fma2(cacc[i][1], ap, wa.y);
                fma2(cacc[i][2], ap, wb.x);
                fma2(cacc[i][3], ap, wb.y);
            }
        }
        __syncthreads();
#pragma unroll
        for (int i = 0; i < 8; i++) {
            int s = ty * 8 + i;
#pragma unroll
            for (int c = 0; c < 4; c++) {
                float2 v = up2(cacc[i][c]);
                int j = tx * 8 + c * 2;
                float v0 = v.x + bc1[j], v1 = v.y + bc1[j + 1];
                h1[s * 257 + j]     = v0 > 0.f ? v0 : 0.f;
                h1[s * 257 + j + 1] = v1 > 0.f ? v1 : 0.f;
            }
        }
        __syncthreads();
    }

    // ---------------- P7: classifier layer 2 (256 -> 80) -------------------
    {
        u64 lacc[8];
        float lex[8];
#pragma unroll
        for (int i = 0; i < 8; i++) { lacc[i] = 0ULL; lex[i] = 0.f; }
#pragma unroll 2
        for (int k = 0; k < 256; k++) {
            u64 w01 = *(const u64*)(Wc2 + (size_t)k * 80 + tx * 2);
            float w2 = (tx < 16) ? Wc2[(size_t)k * 80 + 64 + tx] : 0.f;
#pragma unroll
            for (int i = 0; i < 8; i++) {
                float a = h1[(ty * 8 + i) * 257 + k];
                fma2(lacc[i], pk2(a, a), w01);
                lex[i] = fmaf(a, w2, lex[i]);
            }
        }
#pragma unroll
        for (int i = 0; i < 8; i++) {
            int s = ty * 8 + i;
            size_t r = row0 + sperm[s];
            float2 v = up2(lacc[i]);
            out[r * 80 + tx * 2]     = v.x + bc2[tx * 2];
            out[r * 80 + tx * 2 + 1] = v.y + bc2[tx * 2 + 1];
            if (tx < 16)
                out[r * 80 + 64 + tx] = lex[i] + bc2[64 + tx];
        }
    }
}

// ------------------------------- launch ------------------------------------

extern "C" void kernel_launch(void* const* d_in, const int* in_sizes, int n_in,
                              void* d_out, int out_size) {
    const float* img  = (const float*)d_in[0];
    const float* txt  = (const float*)d_in[1];
    const float* W_ie = (const float*)d_in[2];
    const float* b_ie = (const float*)d_in[3];
    const float* W_te = (const float*)d_in[4];
    const float* b_te = (const float*)d_in[5];
    const float* fq   = (const float*)d_in[6];
    const float* Wq   = (const float*)d_in[7];
    const float* bq   = (const float*)d_in[8];
    const float* Wk   = (const float*)d_in[9];
    const float* bk   = (const float*)d_in[10];
    const float* Wv   = (const float*)d_in[11];
    const float* bv   = (const float*)d_in[12];
    const float* Wo   = (const float*)d_in[13];
    const float* bo   = (const float*)d_in[14];
    const float* W_ip = (const float*)d_in[15];
    const float* b_ip = (const float*)d_in[16];
    const float* W_tp = (const float*)d_in[17];
    const float* b_tp = (const float*)d_in[18];
    const float* W_fp = (const float*)d_in[19];
    const float* b_fp = (const float*)d_in[20];
    const float* Wc1  = (const float*)d_in[21];
    const float* bc1  = (const float*)d_in[22];
    const float* Wc2  = (const float*)d_in[23];
    const float* bc2  = (const float*)d_in[24];
    float* out = (float*)d_out;

    const int B = in_sizes[0] / 512;

    setup_small<<<1, 1024>>>(fq, Wq, bq, Wk, bk, bv, Wo, bo, W_fp, b_fp);
    setup_wof<<<16, 256>>>(Wo, W_fp);

    cudaFuncSetAttribute(fused_main, cudaFuncAttributeMaxDynamicSharedMemorySize,
                         SMEM_BYTES);
    fused_main<<<B / 64, 256, SMEM_BYTES>>>(
        img, txt, W_ie, b_ie, W_te, b_te, Wv,
        W_ip, b_ip, W_tp, b_tp, Wc1, bc1, Wc2, bc2, out);
}

// round 5
// speedup vs baseline: 1.6384x; 1.2377x over previous
#include <cuda_runtime.h>
#include <math.h>

// ---------------------------------------------------------------------------
// AECFModel fused multimodal classifier — fp32 f32x2 FMA, 512 threads/CTA,
// branch sort, head-folded attention. H=256, ID=TD=512, NC=80, B=131072.
// ---------------------------------------------------------------------------

typedef unsigned long long u64;

__device__ __forceinline__ u64 pk2(float x, float y) {
    u64 r; asm("mov.b64 %0,{%1,%2};" : "=l"(r) : "f"(x), "f"(y)); return r;
}
__device__ __forceinline__ void fma2(u64& d, u64 a, u64 b) {
    asm("fma.rn.f32x2 %0,%1,%2,%0;" : "+l"(d) : "l"(a), "l"(b));
}
__device__ __forceinline__ float2 up2(u64 d) {
    float2 r; asm("mov.b64 {%0,%1},%2;" : "=f"(r.x), "=f"(r.y) : "l"(d)); return r;
}

// Per-launch precomputed tensors (device-global scratch; rewritten every call).
__device__ float g_q[256];
__device__ float g_wk[4 * 256];
__device__ float g_ck[4];
__device__ float g_tmp[256];
__device__ float g_Wof[256 * 512];  // Wo @ W_fp
__device__ float g_bof[512];        // (bv@Wo+bo) @ W_fp + b_fp

// ------------------------------ setup kernels ------------------------------

__global__ void setup_small(const float* __restrict__ fq, const float* __restrict__ Wq,
                            const float* __restrict__ bq, const float* __restrict__ Wk,
                            const float* __restrict__ bk, const float* __restrict__ bv,
                            const float* __restrict__ Wo, const float* __restrict__ bo,
                            const float* __restrict__ Wfp, const float* __restrict__ bfp) {
    int t = threadIdx.x;
    if (t < 256) {
        float s = bq[t];
        for (int k = 0; k < 256; k++) s = fmaf(fq[k], Wq[k * 256 + t], s);
        g_q[t] = s;
    }
    __syncthreads();
    {
        int h = t >> 8, j = t & 255;
        float s = 0.f;
#pragma unroll 4
        for (int d = 0; d < 64; d++)
            s = fmaf(Wk[j * 256 + h * 64 + d], g_q[h * 64 + d], s);
        g_wk[h * 256 + j] = s;
        if (t < 4) {
            float c = 0.f;
            for (int d = 0; d < 64; d++) c = fmaf(bk[t * 64 + d], g_q[t * 64 + d], c);
            g_ck[t] = c;
        }
    }
    __syncthreads();
    if (t < 256) {
        float s = bo[t];
        for (int k = 0; k < 256; k++) s = fmaf(bv[k], Wo[k * 256 + t], s);
        g_tmp[t] = s;
    }
    __syncthreads();
    if (t < 512) {
        float s = bfp[t];
        for (int m = 0; m < 256; m++) s = fmaf(g_tmp[m], Wfp[m * 512 + t], s);
        g_bof[t] = s;
    }
}

__global__ void setup_wof(const float* __restrict__ Wo, const float* __restrict__ Wfp) {
    __shared__ float sA[64 * 65];
    int tx = threadIdx.x & 31, ty = threadIdx.x >> 5;
    int it = blockIdx.x >> 2, jt = blockIdx.x & 3;
    float acc[8][4];
#pragma unroll
    for (int i = 0; i < 8; i++)
#pragma unroll
        for (int c = 0; c < 4; c++) acc[i][c] = 0.f;

    for (int mc = 0; mc < 256; mc += 64) {
        __syncthreads();
#pragma unroll
        for (int l = 0; l < 16; l++) {
            int idx = threadIdx.x + l * 256;
            int r = idx >> 6, k = idx & 63;
            sA[r * 65 + k] = Wo[(it * 64 + r) * 256 + mc + k];
        }
        __syncthreads();
#pragma unroll 2
        for (int k = 0; k < 64; k++) {
            const float* Wp = Wfp + (size_t)(mc + k) * 512 + jt * 128 + tx;
            float w[4];
#pragma unroll
            for (int c = 0; c < 4; c++) w[c] = Wp[c * 32];
#pragma unroll
            for (int i = 0; i < 8; i++) {
                float a = sA[(ty * 8 + i) * 65 + k];
#pragma unroll
                for (int c = 0; c < 4; c++) acc[i][c] = fmaf(a, w[c], acc[i][c]);
            }
        }
    }
    __syncthreads();
#pragma unroll
    for (int i = 0; i < 8; i++)
#pragma unroll
        for (int c = 0; c < 4; c++)
            g_Wof[(size_t)(it * 64 + ty * 8 + i) * 512 + jt * 128 + tx + 32 * c] =
                acc[i][c];
}

// ------------------------------- main kernel -------------------------------
// 64 rows/CTA, 512 threads (16 warps). warp w: row-group rg = w&7 (rows rg*8..+7),
// N-half nh = w>>3. 1 CTA/SM (218 KB smem).
//
// smem (float offsets):
//   buf0 @ 0      [64][257] enc_img        buf1 @ 16448 [64][257] enc_txt
//   buf2 @ 32896  [64][257] pooled         sA   @ 49344 [64][65]  (P1 staging)
//   attn @ 53504  [64][4]   flag @ 53760 [64]i  perm @ 53824 [64]i
//   sbr  @ 53888  [64]i     ssq  @ 53952 [512]
//   overlays: fused @ 0 (stride 513), h1 @ 32896 (stride 257)

#define OFF_BUF1 16448
#define OFF_BUF2 32896
#define OFF_SA   49344
#define OFF_ATTN 53504
#define OFF_FLAG 53760
#define OFF_PERM 53824
#define OFF_SBR  53888
#define OFF_SSQ  53952
#define SMEM_FLOATS 54464
#define SMEM_BYTES (SMEM_FLOATS * 4)

// One K=256 x N=512 GEMM segment (this thread's 8 cols at nh*256 + tx*8).
template <bool MASKED>
__device__ __forceinline__ void gemm_seg(u64 (&facc)[8][4],
                                         const float* __restrict__ sm,
                                         const int* aoff,
                                         const float* __restrict__ W,
                                         const float* msk, int nh, int tx) {
    const float* Wb = W + nh * 256 + tx * 8;
#pragma unroll 2
    for (int k = 0; k < 256; k++) {
        const ulonglong2* Wp = (const ulonglong2*)(Wb + (size_t)k * 512);
        ulonglong2 qa = Wp[0], qb = Wp[1];
#pragma unroll
        for (int i = 0; i < 8; i++) {
            float a = sm[aoff[i] + k];
            if (MASKED) a *= msk[i];
            u64 ap = pk2(a, a);
            fma2(facc[i][0], ap, qa.x);
            fma2(facc[i][1], ap, qa.y);
            fma2(facc[i][2], ap, qb.x);
            fma2(facc[i][3], ap, qb.y);
        }
    }
}

__global__ void __launch_bounds__(512)
fused_main(const float* __restrict__ img, const float* __restrict__ txt,
           const float* __restrict__ W_ie, const float* __restrict__ b_ie,
           const float* __restrict__ W_te, const float* __restrict__ b_te,
           const float* __restrict__ Wv,
           const float* __restrict__ W_ip, const float* __restrict__ b_ip,
           const float* __restrict__ W_tp, const float* __restrict__ b_tp,
           const float* __restrict__ Wc1,  const float* __restrict__ bc1,
           const float* __restrict__ Wc2,  const float* __restrict__ bc2,
           float* __restrict__ out) {
    extern __shared__ float sm[];
    float* buf0  = sm;
    float* buf1  = sm + OFF_BUF1;
    float* buf2  = sm + OFF_BUF2;
    float* sA    = sm + OFF_SA;
    float* sattn = sm + OFF_ATTN;
    int*   sflag = (int*)(sm + OFF_FLAG);
    int*   sperm = (int*)(sm + OFF_PERM);
    int*   ssbr  = (int*)(sm + OFF_SBR);
    float* ssq   = sm + OFF_SSQ;
    float* fused = sm;             // stride 513
    float* h1    = sm + OFF_BUF2;  // stride 257

    const int tid = threadIdx.x;
    const int tx = tid & 31;
    const int wp = tid >> 5;       // 0..15
    const int rg = wp & 7;         // row group (8 rows)
    const int nh = wp >> 3;        // N half
    const size_t row0 = (size_t)blockIdx.x * 64;

    // ---------------- P1: encoders + presence flags ------------------------
    for (int mod = 0; mod < 2; mod++) {
        const float* X  = mod ? txt  : img;
        const float* W  = mod ? W_te : W_ie;
        const float* bb = mod ? b_te : b_ie;
        float* enc = mod ? buf1 : buf0;

        u64 acc2[8][2];
#pragma unroll
        for (int i = 0; i < 8; i++) { acc2[i][0] = 0ULL; acc2[i][1] = 0ULL; }
        float sq = 0.f;

        const float* Wb = W + nh * 128 + tx * 4;
        for (int kc = 0; kc < 512; kc += 64) {
            __syncthreads();
#pragma unroll
            for (int l = 0; l < 2; l++) {
                int idx = tid + l * 512;          // 1024 float4 slots
                int r = idx >> 4, k4 = idx & 15;
                float4 v = *(const float4*)(X + (row0 + r) * 512 + kc + k4 * 4);
                float* d = sA + r * 65 + k4 * 4;
                d[0] = v.x; d[1] = v.y; d[2] = v.z; d[3] = v.w;
            }
            __syncthreads();
            {
                int rr = tid >> 3, pp = tid & 7;
#pragma unroll
                for (int u = 0; u < 8; u++) {
                    float v = sA[rr * 65 + pp * 8 + u];
                    sq = fmaf(v, v, sq);
                }
            }
#pragma unroll 2
            for (int k = 0; k < 64; k++) {
                ulonglong2 wv = *(const ulonglong2*)(Wb + (size_t)(kc + k) * 256);
#pragma unroll
                for (int i = 0; i < 8; i++) {
                    float a = sA[(rg * 8 + i) * 65 + k];
                    u64 ap = pk2(a, a);
                    fma2(acc2[i][0], ap, wv.x);
                    fma2(acc2[i][1], ap, wv.y);
                }
            }
        }
#pragma unroll
        for (int i = 0; i < 8; i++) {
            int r = rg * 8 + i;
            int j = nh * 128 + tx * 4;
            float2 va = up2(acc2[i][0]), vb = up2(acc2[i][1]);
            float v0 = va.x + bb[j],     v1 = va.y + bb[j + 1];
            float v2 = vb.x + bb[j + 2], v3 = vb.y + bb[j + 3];
            enc[r * 257 + j]     = v0 > 0.f ? v0 : 0.f;
            enc[r * 257 + j + 1] = v1 > 0.f ? v1 : 0.f;
            enc[r * 257 + j + 2] = v2 > 0.f ? v2 : 0.f;
            enc[r * 257 + j + 3] = v3 > 0.f ? v3 : 0.f;
        }
        __syncthreads();
        ssq[tid] = sq;
        __syncthreads();
        if (tid < 64) {
            float t = 0.f;
#pragma unroll
            for (int p = 0; p < 8; p++) t += ssq[tid * 8 + p];
            int f = (t > 1e-12f) ? 1 : 0;  // norm > 1e-6
            if (mod == 0) sflag[tid] = f;
            else {
                int fi = sflag[tid];
                sflag[tid] = (fi && f) ? 1 : (fi ? 2 : (f ? 3 : 0));
            }
        }
        __syncthreads();
    }

    // ---------------- P2: folded attention scores + softmax ----------------
    if (tid < 256) {
        int r = tid >> 2, h = tid & 3;
        float di = 0.f, dt = 0.f;
        const float* wkp = g_wk + h * 256;
#pragma unroll 4
        for (int j = 0; j < 256; j++) {
            float w = wkp[j];
            di = fmaf(buf0[r * 257 + j], w, di);
            dt = fmaf(buf1[r * 257 + j], w, dt);
        }
        float s0 = (di + g_ck[h]) * 0.125f;
        float s1 = (dt + g_ck[h]) * 0.125f;
        float m  = fmaxf(s0, s1);
        float e0 = expf(s0 - m), e1 = expf(s1 - m);
        sattn[r * 4 + h] = e0 / (e0 + e1);  // a0; a1 = 1 - a0
    }
    // branch counting sort: order both(1), img(2), txt(3), none(0)
    if (tid == 511) {
        int cnt[4] = {0, 0, 0, 0};
        for (int r = 0; r < 64; r++) cnt[sflag[r]]++;
        int base[4];
        base[1] = 0;
        base[2] = cnt[1];
        base[3] = cnt[1] + cnt[2];
        base[0] = cnt[1] + cnt[2] + cnt[3];
        for (int r = 0; r < 64; r++) {
            int f = sflag[r];
            int s = base[f]++;
            sperm[s] = r;
            ssbr[s]  = f;
        }
    }
    __syncthreads();

    // ---------------- P3: pooled = e1@Wv + a0(h) * ((e0-e1)@Wv) ------------
    {
        u64 pt[8][2], pd[8][2];
#pragma unroll
        for (int i = 0; i < 8; i++) {
            pt[i][0] = pt[i][1] = 0ULL;
            pd[i][0] = pd[i][1] = 0ULL;
        }
        const float* Wb = Wv + nh * 128 + tx * 4;
#pragma unroll 2
        for (int k = 0; k < 256; k++) {
            ulonglong2 wv = *(const ulonglong2*)(Wb + (size_t)k * 256);
#pragma unroll
            for (int i = 0; i < 8; i++) {
                int r = rg * 8 + i;
                float e0 = buf0[r * 257 + k];
                float e1 = buf1[r * 257 + k];
                float d  = e0 - e1;
                u64 a1 = pk2(e1, e1);
                u64 a2 = pk2(d, d);
                fma2(pt[i][0], a1, wv.x);
                fma2(pt[i][1], a1, wv.y);
                fma2(pd[i][0], a2, wv.x);
                fma2(pd[i][1], a2, wv.y);
            }
        }
        int j = nh * 128 + tx * 4;
        int h = j >> 6;
#pragma unroll
        for (int i = 0; i < 8; i++) {
            int r = rg * 8 + i;
            float a0 = sattn[r * 4 + h];
            float2 t0 = up2(pt[i][0]), t1 = up2(pt[i][1]);
            float2 d0 = up2(pd[i][0]), d1 = up2(pd[i][1]);
            buf2[r * 257 + j]     = fmaf(a0, d0.x, t0.x);
            buf2[r * 257 + j + 1] = fmaf(a0, d0.y, t0.y);
            buf2[r * 257 + j + 2] = fmaf(a0, d1.x, t1.x);
            buf2[r * 257 + j + 3] = fmaf(a0, d1.y, t1.y);
        }
    }
    __syncthreads();

    // ---------------- P5: branch-specialized projection GEMM ---------------
    u64 facc[8][4];
#pragma unroll
    for (int i = 0; i < 8; i++)
#pragma unroll
        for (int u = 0; u < 4; u++) facc[i][u] = 0ULL;

    {
        int aoff[8];
        int br[8];
#pragma unroll
        for (int i = 0; i < 8; i++) {
            aoff[i] = sperm[rg * 8 + i] * 257;
            br[i]   = ssbr[rg * 8 + i];
        }
        if (br[0] == br[7]) {
            if (br[0] == 1)
                gemm_seg<false>(facc, buf2, aoff, g_Wof, 0, nh, tx);
            else if (br[0] == 2)
                gemm_seg<false>(facc, buf0, aoff, W_ip, 0, nh, tx);
            else if (br[0] == 3)
                gemm_seg<false>(facc, buf1, aoff, W_tp, 0, nh, tx);
        } else {
            unsigned need = 0;
#pragma unroll
            for (int i = 0; i < 8; i++) need |= 1u << br[i];
            float msk[8];
            for (int seg = 1; seg <= 3; seg++) {
                if (!(need & (1u << seg))) continue;
#pragma unroll
                for (int i = 0; i < 8; i++) msk[i] = (br[i] == seg) ? 1.f : 0.f;
                const float* A = (seg == 1) ? buf2 : (seg == 2) ? buf0 : buf1;
                const float* W = (seg == 1) ? g_Wof : (seg == 2) ? W_ip : W_tp;
                gemm_seg<true>(facc, A, aoff, W, msk, nh, tx);
            }
        }
    }
    __syncthreads();  // all buf reads done before fused overlay write
#pragma unroll
    for (int i = 0; i < 8; i++) {
        int s = rg * 8 + i;
        int fl = ssbr[s];
        const float* bsel = (fl == 1) ? g_bof : (fl == 2) ? b_ip
                          : (fl == 3) ? b_tp : (const float*)0;
#pragma unroll
        for (int u = 0; u < 4; u++) {
            float2 v = up2(facc[i][u]);
            int j = nh * 256 + tx * 8 + u * 2;
            float b0 = bsel ? bsel[j] : 0.f;
            float b1 = bsel ? bsel[j + 1] : 0.f;
            fused[s * 513 + j]     = v.x + b0;
            fused[s * 513 + j + 1] = v.y + b1;
        }
    }
    __syncthreads();

    // ---------------- P6: classifier layer 1 (512 -> 256, ReLU) ------------
    {
        u64 cacc[8][2];
#pragma unroll
        for (int i = 0; i < 8; i++) { cacc[i][0] = 0ULL; cacc[i][1] = 0ULL; }
        const float* Wb = Wc1 + nh * 128 + tx * 4;
#pragma unroll 2
        for (int k = 0; k < 512; k++) {
            ulonglong2 wv = *(const ulonglong2*)(Wb + (size_t)k * 256);
#pragma unroll
            for (int i = 0; i < 8; i++) {
                float a = fused[(rg * 8 + i) * 513 + k];
                u64 ap = pk2(a, a);
                fma2(cacc[i][0], ap, wv.x);
                fma2(cacc[i][1], ap, wv.y);
            }
        }
        __syncthreads();
#pragma unroll
        for (int i = 0; i < 8; i++) {
            int s = rg * 8 + i;
            int j = nh * 128 + tx * 4;
            float2 va = up2(cacc[i][0]), vb = up2(cacc[i][1]);
            float v0 = va.x + bc1[j],     v1 = va.y + bc1[j + 1];
            float v2 = vb.x + bc1[j + 2], v3 = vb.y + bc1[j + 3];
            h1[s * 257 + j]     = v0 > 0.f ? v0 : 0.f;
            h1[s * 257 + j + 1] = v1 > 0.f ? v1 : 0.f;
            h1[s * 257 + j + 2] = v2 > 0.f ? v2 : 0.f;
            h1[s * 257 + j + 3] = v3 > 0.f ? v3 : 0.f;
        }
        __syncthreads();
    }

    // ---------------- P7: classifier layer 2 (256 -> 80) -------------------
    if (nh == 0) {
        u64 lacc[8];
#pragma unroll
        for (int i = 0; i < 8; i++) lacc[i] = 0ULL;
#pragma unroll 2
        for (int k = 0; k < 256; k++) {
            u64 w01 = *(const u64*)(Wc2 + (size_t)k * 80 + tx * 2);
#pragma unroll
            for (int i = 0; i < 8; i++) {
                float a = h1[(rg * 8 + i) * 257 + k];
                fma2(lacc[i], pk2(a, a), w01);
            }
        }
#pragma unroll
        for (int i = 0; i < 8; i++) {
            int s = rg * 8 + i;
            size_t r = row0 + sperm[s];
            float2 v = up2(lacc[i]);
            out[r * 80 + tx * 2]     = v.x + bc2[tx * 2];
            out[r * 80 + tx * 2 + 1] = v.y + bc2[tx * 2 + 1];
        }
    } else {
        float lex[8];
#pragma unroll
        for (int i = 0; i < 8; i++) lex[i] = 0.f;
#pragma unroll 2
        for (int k = 0; k < 256; k++) {
            float w2 = (tx < 16) ? Wc2[(size_t)k * 80 + 64 + tx] : 0.f;
#pragma unroll
            for (int i = 0; i < 8; i++) {
                float a = h1[(rg * 8 + i) * 257 + k];
                lex[i] = fmaf(a, w2, lex[i]);
            }
        }
        if (tx < 16) {
#pragma unroll
            for (int i = 0; i < 8; i++) {
                int s = rg * 8 + i;
                size_t r = row0 + sperm[s];
                out[r * 80 + 64 + tx] = lex[i] + bc2[64 + tx];
            }
        }
    }
}

// ------------------------------- launch ------------------------------------

extern "C" void kernel_launch(void* const* d_in, const int* in_sizes, int n_in,
                              void* d_out, int out_size) {
    const float* img  = (const float*)d_in[0];
    const float* txt  = (const float*)d_in[1];
    const float* W_ie = (const float*)d_in[2];
    const float* b_ie = (const float*)d_in[3];
    const float* W_te = (const float*)d_in[4];
    const float* b_te = (const float*)d_in[5];
    const float* fq   = (const float*)d_in[6];
    const float* Wq   = (const float*)d_in[7];
    const float* bq   = (const float*)d_in[8];
    const float* Wk   = (const float*)d_in[9];
    const float* bk   = (const float*)d_in[10];
    const float* Wv   = (const float*)d_in[11];
    const float* bv   = (const float*)d_in[12];
    const float* Wo   = (const float*)d_in[13];
    const float* bo   = (const float*)d_in[14];
    const float* W_ip = (const float*)d_in[15];
    const float* b_ip = (const float*)d_in[16];
    const float* W_tp = (const float*)d_in[17];
    const float* b_tp = (const float*)d_in[18];
    const float* W_fp = (const float*)d_in[19];
    const float* b_fp = (const float*)d_in[20];
    const float* Wc1  = (const float*)d_in[21];
    const float* bc1  = (const float*)d_in[22];
    const float* Wc2  = (const float*)d_in[23];
    const float* bc2  = (const float*)d_in[24];
    float* out = (float*)d_out;

    const int B = in_sizes[0] / 512;

    setup_small<<<1, 1024>>>(fq, Wq, bq, Wk, bk, bv, Wo, bo, W_fp, b_fp);
    setup_wof<<<16, 256>>>(Wo, W_fp);

    cudaFuncSetAttribute(fused_main, cudaFuncAttributeMaxDynamicSharedMemorySize,
                         SMEM_BYTES);
    fused_main<<<B / 64, 512, SMEM_BYTES>>>(
        img, txt, W_ie, b_ie, W_te, b_te, Wv,
        W_ip, b_ip, W_tp, b_tp, Wc1, bc1, Wc2, bc2, out);
}

// round 6
// speedup vs baseline: 2.0468x; 1.2493x over previous
#include <cuda_runtime.h>
#include <math.h>

// ---------------------------------------------------------------------------
// AECFModel fused multimodal classifier — fp32, row-pair f32x2 FMA on
// transposed smem tiles, pre-sorted branches. H=256, ID=TD=512, NC=80.
// ---------------------------------------------------------------------------

typedef unsigned long long u64;

__device__ __forceinline__ u64 pk2(float x, float y) {
    u64 r; asm("mov.b64 %0,{%1,%2};" : "=l"(r) : "f"(x), "f"(y)); return r;
}
__device__ __forceinline__ void fma2(u64& d, u64 a, u64 b) {
    asm("fma.rn.f32x2 %0,%1,%2,%0;" : "+l"(d) : "l"(a), "l"(b));
}
__device__ __forceinline__ u64 mul2(u64 a, u64 b) {
    u64 r; asm("mul.rn.f32x2 %0,%1,%2;" : "=l"(r) : "l"(a), "l"(b)); return r;
}
__device__ __forceinline__ float2 up2(u64 d) {
    float2 r; asm("mov.b64 {%0,%1},%2;" : "=f"(r.x), "=f"(r.y) : "l"(d)); return r;
}

// Per-launch precomputed tensors (device-global scratch; rewritten every call).
__device__ float g_q[256];
__device__ float g_wk[4 * 256];
__device__ float g_ck[4];
__device__ float g_tmp[256];
__device__ float g_Wof[256 * 512];  // Wo @ W_fp
__device__ float g_bof[512];        // (bv@Wo+bo) @ W_fp + b_fp

// ---------------------------- combined setup -------------------------------
// grid 17 x 256. Block 0: small precomputes. Blocks 1..16: Wof tiles.
__global__ void setup_all(const float* __restrict__ fq, const float* __restrict__ Wq,
                          const float* __restrict__ bq, const float* __restrict__ Wk,
                          const float* __restrict__ bk, const float* __restrict__ bv,
                          const float* __restrict__ Wo, const float* __restrict__ bo,
                          const float* __restrict__ Wfp, const float* __restrict__ bfp) {
    __shared__ float sA[64 * 65];
    int t = threadIdx.x;
    if (blockIdx.x == 0) {
        {   // g_q
            float s = bq[t];
#pragma unroll 8
            for (int k = 0; k < 256; k++) s = fmaf(fq[k], Wq[k * 256 + t], s);
            g_q[t] = s;
        }
        __syncthreads();
#pragma unroll
        for (int l = 0; l < 4; l++) {   // g_wk
            int idx = t + l * 256;
            int h = idx >> 8, j = idx & 255;
            float s = 0.f;
#pragma unroll 8
            for (int d = 0; d < 64; d++)
                s = fmaf(Wk[j * 256 + h * 64 + d], g_q[h * 64 + d], s);
            g_wk[h * 256 + j] = s;
        }
        if (t < 4) {                    // g_ck
            float c = 0.f;
#pragma unroll 8
            for (int d = 0; d < 64; d++) c = fmaf(bk[t * 64 + d], g_q[t * 64 + d], c);
            g_ck[t] = c;
        }
        __syncthreads();
        {   // g_tmp = bv@Wo + bo
            float s = bo[t];
#pragma unroll 8
            for (int k = 0; k < 256; k++) s = fmaf(bv[k], Wo[k * 256 + t], s);
            g_tmp[t] = s;
        }
        __syncthreads();
#pragma unroll
        for (int l = 0; l < 2; l++) {   // g_bof
            int j = t + l * 256;
            float s = bfp[j];
#pragma unroll 8
            for (int m = 0; m < 256; m++) s = fmaf(g_tmp[m], Wfp[m * 512 + j], s);
            g_bof[j] = s;
        }
        return;
    }
    // ---- Wof tile ----
    int bid = blockIdx.x - 1;
    int tx = t & 31, ty = t >> 5;
    int it = bid >> 2, jt = bid & 3;
    float acc[8][4];
#pragma unroll
    for (int i = 0; i < 8; i++)
#pragma unroll
        for (int c = 0; c < 4; c++) acc[i][c] = 0.f;

    for (int mc = 0; mc < 256; mc += 64) {
        __syncthreads();
#pragma unroll
        for (int l = 0; l < 16; l++) {
            int idx = t + l * 256;
            int r = idx >> 6, k = idx & 63;
            sA[r * 65 + k] = Wo[(it * 64 + r) * 256 + mc + k];
        }
        __syncthreads();
#pragma unroll 2
        for (int k = 0; k < 64; k++) {
            const float* Wp = Wfp + (size_t)(mc + k) * 512 + jt * 128 + tx;
            float w[4];
#pragma unroll
            for (int c = 0; c < 4; c++) w[c] = Wp[c * 32];
#pragma unroll
            for (int i = 0; i < 8; i++) {
                float a = sA[(ty * 8 + i) * 65 + k];
#pragma unroll
                for (int c = 0; c < 4; c++) acc[i][c] = fmaf(a, w[c], acc[i][c]);
            }
        }
    }
    __syncthreads();
#pragma unroll
    for (int i = 0; i < 8; i++)
#pragma unroll
        for (int c = 0; c < 4; c++)
            g_Wof[(size_t)(it * 64 + ty * 8 + i) * 512 + jt * 128 + tx + 32 * c] =
                acc[i][c];
}

// ------------------------------- main kernel -------------------------------
// 64 rows/CTA (sorted slots), 512 threads (16 warps).
// warp w: rg = w&7 (slots rg*8..+7 as 4 row-pairs), nh = w>>3 (N half).
// All smem tensors transposed [k][slot], stride 66 (even -> LDS.64 pairs).
//
// smem (float offsets):
//   e0T @ 0      [256][66]   e1T @ 16896 [256][66]   pT @ 33792 [256][66]
//   sAT @ 50688  [64][66] staging (also norm partials pre-pass)
//   attn @ 54912 [64][4] (by slot)   flag @ 55168  perm @ 55232  sbr @ 55296
//   overlays: fusedT @ 0 [512][66] (= e0T+e1T exactly), h1T @ 33792 [256][66]

#define S66 66
#define OFF_E1   16896
#define OFF_PT   33792
#define OFF_SAT  50688
#define OFF_ATTN 54912
#define OFF_FLAG 55168
#define OFF_PERM 55232
#define OFF_SBR  55296
#define SMEM_FLOATS 55360
#define SMEM_BYTES (SMEM_FLOATS * 4)

// P5 segment: K=256 -> this thread's 8 cols (nh*256 + tx*8). Row-pair A from AT.
template <bool MASKED>
__device__ __forceinline__ void gemm_seg(u64 (&facc)[4][8],
                                         const float* __restrict__ AT,
                                         const float* __restrict__ W,
                                         const u64* mp, int rg, int nh, int tx) {
    const float* Wb = W + nh * 256 + tx * 8;
    const float* Ab = AT + rg * 8;
#pragma unroll 2
    for (int k = 0; k < 256; k++) {
        float4 wa = *(const float4*)(Wb + (size_t)k * 512);
        float4 wb = *(const float4*)(Wb + (size_t)k * 512 + 4);
        u64 wp[8] = {pk2(wa.x, wa.x), pk2(wa.y, wa.y), pk2(wa.z, wa.z), pk2(wa.w, wa.w),
                     pk2(wb.x, wb.x), pk2(wb.y, wb.y), pk2(wb.z, wb.z), pk2(wb.w, wb.w)};
        const float* ab = Ab + k * S66;
#pragma unroll
        for (int p = 0; p < 4; p++) {
            u64 ap = *(const u64*)(ab + 2 * p);
            if (MASKED) ap = mul2(ap, mp[p]);
#pragma unroll
            for (int c = 0; c < 8; c++) fma2(facc[p][c], ap, wp[c]);
        }
    }
}

__global__ void __launch_bounds__(512)
fused_main(const float* __restrict__ img, const float* __restrict__ txt,
           const float* __restrict__ W_ie, const float* __restrict__ b_ie,
           const float* __restrict__ W_te, const float* __restrict__ b_te,
           const float* __restrict__ Wv,
           const float* __restrict__ W_ip, const float* __restrict__ b_ip,
           const float* __restrict__ W_tp, const float* __restrict__ b_tp,
           const float* __restrict__ Wc1,  const float* __restrict__ bc1,
           const float* __restrict__ Wc2,  const float* __restrict__ bc2,
           float* __restrict__ out) {
    extern __shared__ float sm[];
    float* e0T   = sm;
    float* e1T   = sm + OFF_E1;
    float* pT    = sm + OFF_PT;
    float* sAT   = sm + OFF_SAT;
    float* sattn = sm + OFF_ATTN;
    int*   sflag = (int*)(sm + OFF_FLAG);
    int*   sperm = (int*)(sm + OFF_PERM);
    int*   ssbr  = (int*)(sm + OFF_SBR);
    float* fusedT = sm;            // [512][66]
    float* h1T    = sm + OFF_PT;   // [256][66]

    const int tid = threadIdx.x;
    const int tx = tid & 31;
    const int wp = tid >> 5;
    const int rg = wp & 7;
    const int nh = wp >> 3;
    const size_t row0 = (size_t)blockIdx.x * 64;

    // ---------------- P0: presence flags + branch counting sort ------------
    {
        float* npart = sAT;  // [2][64][8]
#pragma unroll
        for (int l = 0; l < 2; l++) {
            int task = tid + l * 512;
            int mod = task >> 9, r = (task >> 3) & 63, p = task & 7;
            const float* X = mod ? txt : img;
            const float4* xp = (const float4*)(X + (row0 + r) * 512 + p * 64);
            float s = 0.f;
#pragma unroll
            for (int u = 0; u < 16; u++) {
                float4 v = xp[u];
                s += v.x * v.x + v.y * v.y + v.z * v.z + v.w * v.w;
            }
            npart[task] = s;
        }
        __syncthreads();
        if (tid < 64) {
            float si = 0.f, st = 0.f;
#pragma unroll
            for (int p = 0; p < 8; p++) {
                si += npart[tid * 8 + p];
                st += npart[512 + tid * 8 + p];
            }
            int fi = si > 1e-12f, ft = st > 1e-12f;  // norm > 1e-6
            sflag[tid] = (fi && ft) ? 1 : (fi ? 2 : (ft ? 3 : 0));
        }
        __syncthreads();
        if (tid == 0) {  // counting sort: both(1), img(2), txt(3), none(0)
            int cnt[4] = {0, 0, 0, 0};
            for (int r = 0; r < 64; r++) cnt[sflag[r]]++;
            int base[4];
            base[1] = 0;
            base[2] = cnt[1];
            base[3] = cnt[1] + cnt[2];
            base[0] = cnt[1] + cnt[2] + cnt[3];
            for (int r = 0; r < 64; r++) {
                int f = sflag[r];
                int s = base[f]++;
                sperm[s] = r;
                ssbr[s]  = f;
            }
        }
        __syncthreads();
    }

    // ---------------- P1: encoders (transposed, sorted) --------------------
    for (int mod = 0; mod < 2; mod++) {
        const float* X  = mod ? txt  : img;
        const float* W  = mod ? W_te : W_ie;
        const float* bb = mod ? b_te : b_ie;
        float* eT = mod ? e1T : e0T;

        u64 acc[4][4];
#pragma unroll
        for (int p = 0; p < 4; p++)
#pragma unroll
            for (int c = 0; c < 4; c++) acc[p][c] = 0ULL;

        const float* Wb = W + nh * 128 + tx * 4;
        for (int kc = 0; kc < 512; kc += 64) {
            __syncthreads();
#pragma unroll
            for (int l = 0; l < 2; l++) {
                int idx = tid + l * 512;
                int s = idx >> 4, k4 = idx & 15;
                float4 v = *(const float4*)(X + (row0 + sperm[s]) * 512 + kc + k4 * 4);
                float* d = sAT + (k4 * 4) * S66 + s;
                d[0] = v.x; d[S66] = v.y; d[2 * S66] = v.z; d[3 * S66] = v.w;
            }
            __syncthreads();
#pragma unroll 4
            for (int k = 0; k < 64; k++) {
                float4 w = *(const float4*)(Wb + (size_t)(kc + k) * 256);
                u64 w0 = pk2(w.x, w.x), w1 = pk2(w.y, w.y);
                u64 w2 = pk2(w.z, w.z), w3 = pk2(w.w, w.w);
                const float* ab = sAT + k * S66 + rg * 8;
#pragma unroll
                for (int p = 0; p < 4; p++) {
                    u64 ap = *(const u64*)(ab + 2 * p);
                    fma2(acc[p][0], ap, w0);
                    fma2(acc[p][1], ap, w1);
                    fma2(acc[p][2], ap, w2);
                    fma2(acc[p][3], ap, w3);
                }
            }
        }
#pragma unroll
        for (int p = 0; p < 4; p++)
#pragma unroll
            for (int c = 0; c < 4; c++) {
                int j = nh * 128 + tx * 4 + c;
                float b = bb[j];
                float2 v = up2(acc[p][c]);
                float r0 = v.x + b, r1 = v.y + b;
                r0 = r0 > 0.f ? r0 : 0.f;
                r1 = r1 > 0.f ? r1 : 0.f;
                *(float2*)(eT + j * S66 + rg * 8 + 2 * p) = make_float2(r0, r1);
            }
    }
    __syncthreads();

    // ---------------- P2: folded attention scores + softmax ----------------
    if (tid < 256) {
        int s = tid >> 2, h = tid & 3;
        float di = 0.f, dt = 0.f;
        const float* wkp = g_wk + h * 256;
#pragma unroll 4
        for (int j = 0; j < 256; j++) {
            float w = wkp[j];
            di = fmaf(e0T[j * S66 + s], w, di);
            dt = fmaf(e1T[j * S66 + s], w, dt);
        }
        float s0 = (di + g_ck[h]) * 0.125f;
        float s1 = (dt + g_ck[h]) * 0.125f;
        float m  = fmaxf(s0, s1);
        float e0 = expf(s0 - m), e1 = expf(s1 - m);
        sattn[s * 4 + h] = e0 / (e0 + e1);  // weight on image slot
    }
    __syncthreads();

    // ---------------- P3: pooled = lerp(e1@Wv, e0@Wv, a0) ------------------
    {
        u64 q0[4][4], q1[4][4];
#pragma unroll
        for (int p = 0; p < 4; p++)
#pragma unroll
            for (int c = 0; c < 4; c++) { q0[p][c] = 0ULL; q1[p][c] = 0ULL; }

        const float* Wb = Wv + nh * 128 + tx * 4;
#pragma unroll 2
        for (int k = 0; k < 256; k++) {
            float4 w = *(const float4*)(Wb + (size_t)k * 256);
            u64 w0 = pk2(w.x, w.x), w1 = pk2(w.y, w.y);
            u64 w2 = pk2(w.z, w.z), w3 = pk2(w.w, w.w);
            const float* a0b = e0T + k * S66 + rg * 8;
            const float* a1b = e1T + k * S66 + rg * 8;
#pragma unroll
            for (int p = 0; p < 4; p++) {
                u64 ap0 = *(const u64*)(a0b + 2 * p);
                u64 ap1 = *(const u64*)(a1b + 2 * p);
                fma2(q0[p][0], ap0, w0); fma2(q1[p][0], ap1, w0);
                fma2(q0[p][1], ap0, w1); fma2(q1[p][1], ap1, w1);
                fma2(q0[p][2], ap0, w2); fma2(q1[p][2], ap1, w2);
                fma2(q0[p][3], ap0, w3); fma2(q1[p][3], ap1, w3);
            }
        }
#pragma unroll
        for (int p = 0; p < 4; p++) {
            int s0 = rg * 8 + 2 * p;
#pragma unroll
            for (int c = 0; c < 4; c++) {
                int j = nh * 128 + tx * 4 + c;
                int h = j >> 6;
                float a00 = sattn[s0 * 4 + h], a01 = sattn[(s0 + 1) * 4 + h];
                float2 v0 = up2(q0[p][c]), v1 = up2(q1[p][c]);
                float r0 = fmaf(a00, v0.x - v1.x, v1.x);
                float r1 = fmaf(a01, v0.y - v1.y, v1.y);
                *(float2*)(pT + j * S66 + s0) = make_float2(r0, r1);
            }
        }
    }
    __syncthreads();

    // ---------------- P5: branch-specialized projection GEMM ---------------
    {
        u64 facc[4][8];
#pragma unroll
        for (int p = 0; p < 4; p++)
#pragma unroll
            for (int c = 0; c < 8; c++) facc[p][c] = 0ULL;

        int br[8];
#pragma unroll
        for (int i = 0; i < 8; i++) br[i] = ssbr[rg * 8 + i];

        if (br[0] == br[7]) {
            if (br[0] == 1)      gemm_seg<false>(facc, pT,  g_Wof, 0, rg, nh, tx);
            else if (br[0] == 2) gemm_seg<false>(facc, e0T, W_ip,  0, rg, nh, tx);
            else if (br[0] == 3) gemm_seg<false>(facc, e1T, W_tp,  0, rg, nh, tx);
        } else {
            unsigned need = 0;
#pragma unroll
            for (int i = 0; i < 8; i++) need |= 1u << br[i];
            for (int seg = 1; seg <= 3; seg++) {
                if (!(need & (1u << seg))) continue;
                u64 mp[4];
#pragma unroll
                for (int p = 0; p < 4; p++)
                    mp[p] = pk2(br[2 * p] == seg ? 1.f : 0.f,
                                br[2 * p + 1] == seg ? 1.f : 0.f);
                const float* A = (seg == 1) ? pT : (seg == 2) ? e0T : e1T;
                const float* W = (seg == 1) ? g_Wof : (seg == 2) ? W_ip : W_tp;
                gemm_seg<true>(facc, A, W, mp, rg, nh, tx);
            }
        }
        __syncthreads();  // all smem reads done before fusedT overlay write
#pragma unroll
        for (int p = 0; p < 4; p++) {
            int s0 = rg * 8 + 2 * p;
            int f0 = ssbr[s0], f1 = ssbr[s0 + 1];
            const float* b0p = (f0 == 1) ? g_bof : (f0 == 2) ? b_ip
                             : (f0 == 3) ? b_tp : (const float*)0;
            const float* b1p = (f1 == 1) ? g_bof : (f1 == 2) ? b_ip
                             : (f1 == 3) ? b_tp : (const float*)0;
#pragma unroll
            for (int c = 0; c < 8; c++) {
                int j = nh * 256 + tx * 8 + c;
                float2 v = up2(facc[p][c]);
                float r0 = v.x + (b0p ? b0p[j] : 0.f);
                float r1 = v.y + (b1p ? b1p[j] : 0.f);
                *(float2*)(fusedT + j * S66 + s0) = make_float2(r0, r1);
            }
        }
        __syncthreads();
    }

    // ---------------- P6: classifier layer 1 (512 -> 256, ReLU) ------------
    {
        u64 cacc[4][4];
#pragma unroll
        for (int p = 0; p < 4; p++)
#pragma unroll
            for (int c = 0; c < 4; c++) cacc[p][c] = 0ULL;

        const float* Wb = Wc1 + nh * 128 + tx * 4;
#pragma unroll 4
        for (int k = 0; k < 512; k++) {
            float4 w = *(const float4*)(Wb + (size_t)k * 256);
            u64 w0 = pk2(w.x, w.x), w1 = pk2(w.y, w.y);
            u64 w2 = pk2(w.z, w.z), w3 = pk2(w.w, w.w);
            const float* ab = fusedT + k * S66 + rg * 8;
#pragma unroll
            for (int p = 0; p < 4; p++) {
                u64 ap = *(const u64*)(ab + 2 * p);
                fma2(cacc[p][0], ap, w0);
                fma2(cacc[p][1], ap, w1);
                fma2(cacc[p][2], ap, w2);
                fma2(cacc[p][3], ap, w3);
            }
        }
        __syncthreads();  // fusedT reads done before h1T overlay write (pT dead)
#pragma unroll
        for (int p = 0; p < 4; p++)
#pragma unroll
            for (int c = 0; c < 4; c++) {
                int j = nh * 128 + tx * 4 + c;
                float b = bc1[j];
                float2 v = up2(cacc[p][c]);
                float r0 = v.x + b, r1 = v.y + b;
                r0 = r0 > 0.f ? r0 : 0.f;
                r1 = r1 > 0.f ? r1 : 0.f;
                *(float2*)(h1T + j * S66 + rg * 8 + 2 * p) = make_float2(r0, r1);
            }
        __syncthreads();
    }

    // ---------------- P7: classifier layer 2 (256 -> 80) -------------------
    if (nh == 0) {
        u64 lacc[4][2];
#pragma unroll
        for (int p = 0; p < 4; p++) { lacc[p][0] = 0ULL; lacc[p][1] = 0ULL; }
#pragma unroll 2
        for (int k = 0; k < 256; k++) {
            float2 w = *(const float2*)(Wc2 + (size_t)k * 80 + tx * 2);
            u64 w0 = pk2(w.x, w.x), w1 = pk2(w.y, w.y);
            const float* ab = h1T + k * S66 + rg * 8;
#pragma unroll
            for (int p = 0; p < 4; p++) {
                u64 ap = *(const u64*)(ab + 2 * p);
                fma2(lacc[p][0], ap, w0);
                fma2(lacc[p][1], ap, w1);
            }
        }
#pragma unroll
        for (int p = 0; p < 4; p++) {
            int s0 = rg * 8 + 2 * p;
            size_t r0o = (row0 + sperm[s0]) * 80;
            size_t r1o = (row0 + sperm[s0 + 1]) * 80;
#pragma unroll
            for (int c = 0; c < 2; c++) {
                int j = tx * 2 + c;
                float2 v = up2(lacc[p][c]);
                out[r0o + j] = v.x + bc2[j];
                out[r1o + j] = v.y + bc2[j];
            }
        }
    } else {
        u64 lacc[4];
#pragma unroll
        for (int p = 0; p < 4; p++) lacc[p] = 0ULL;
#pragma unroll 2
        for (int k = 0; k < 256; k++) {
            float w = (tx < 16) ? Wc2[(size_t)k * 80 + 64 + tx] : 0.f;
            u64 w0 = pk2(w, w);
            const float* ab = h1T + k * S66 + rg * 8;
#pragma unroll
            for (int p = 0; p < 4; p++) {
                u64 ap = *(const u64*)(ab + 2 * p);
                fma2(lacc[p], ap, w0);
            }
        }
        if (tx < 16) {
            int j = 64 + tx;
#pragma unroll
            for (int p = 0; p < 4; p++) {
                int s0 = rg * 8 + 2 * p;
                float2 v = up2(lacc[p]);
                out[(row0 + sperm[s0]) * 80 + j]     = v.x + bc2[j];
                out[(row0 + sperm[s0 + 1]) * 80 + j] = v.y + bc2[j];
            }
        }
    }
}

// ------------------------------- launch ------------------------------------

extern "C" void kernel_launch(void* const* d_in, const int* in_sizes, int n_in,
                              void* d_out, int out_size) {
    const float* img  = (const float*)d_in[0];
    const float* txt  = (const float*)d_in[1];
    const float* W_ie = (const float*)d_in[2];
    const float* b_ie = (const float*)d_in[3];
    const float* W_te = (const float*)d_in[4];
    const float* b_te = (const float*)d_in[5];
    const float* fq   = (const float*)d_in[6];
    const float* Wq   = (const float*)d_in[7];
    const float* bq   = (const float*)d_in[8];
    const float* Wk   = (const float*)d_in[9];
    const float* bk   = (const float*)d_in[10];
    const float* Wv   = (const float*)d_in[11];
    const float* bv   = (const float*)d_in[12];
    const float* Wo   = (const float*)d_in[13];
    const float* bo   = (const float*)d_in[14];
    const float* W_ip = (const float*)d_in[15];
    const float* b_ip = (const float*)d_in[16];
    const float* W_tp = (const float*)d_in[17];
    const float* b_tp = (const float*)d_in[18];
    const float* W_fp = (const float*)d_in[19];
    const float* b_fp = (const float*)d_in[20];
    const float* Wc1  = (const float*)d_in[21];
    const float* bc1  = (const float*)d_in[22];
    const float* Wc2  = (const float*)d_in[23];
    const float* bc2  = (const float*)d_in[24];
    float* out = (float*)d_out;

    const int B = in_sizes[0] / 512;

    setup_all<<<17, 256>>>(fq, Wq, bq, Wk, bk, bv, Wo, bo, W_fp, b_fp);

    cudaFuncSetAttribute(fused_main, cudaFuncAttributeMaxDynamicSharedMemorySize,
                         SMEM_BYTES);
    fused_main<<<B / 64, 512, SMEM_BYTES>>>(
        img, txt, W_ie, b_ie, W_te, b_te, Wv,
        W_ip, b_ip, W_tp, b_tp, Wc1, bc1, Wc2, bc2, out);
}